// round 3
// baseline (speedup 1.0000x reference)
#include <cuda_runtime.h>

#define D        256
#define TM       64
#define TN       256
#define BK       32
#define NMAX     8192
#define NTHREADS 512

__device__ float g_esq[NMAX];

// ---------------------------------------------------------------------------
// Prepass: e_sq[n] = sum_d embed[n][d]^2.  One warp per code row.
// ---------------------------------------------------------------------------
__global__ void esq_kernel(const float* __restrict__ embed, int N) {
    int warp = (blockIdx.x * blockDim.x + threadIdx.x) >> 5;
    int lane = threadIdx.x & 31;
    if (warp >= N) return;
    const float4* row = (const float4*)(embed + (size_t)warp * D);
    float s = 0.f;
    #pragma unroll
    for (int i = lane; i < D / 4; i += 32) {
        float4 v = row[i];
        s += v.x * v.x + v.y * v.y + v.z * v.z + v.w * v.w;
    }
    #pragma unroll
    for (int o = 16; o; o >>= 1) s += __shfl_xor_sync(0xFFFFFFFFu, s, o);
    if (lane == 0) g_esq[warp] = s;
}

// ---------------------------------------------------------------------------
// Packed f32x2 helpers
// ---------------------------------------------------------------------------
__device__ __forceinline__ unsigned long long pack_dup(float a) {
    unsigned long long r;
    unsigned ai = __float_as_uint(a);
    asm("mov.b64 %0, {%1, %1};" : "=l"(r) : "r"(ai));
    return r;
}
__device__ __forceinline__ void fma2(unsigned long long& acc,
                                     unsigned long long a,
                                     unsigned long long b) {
    asm("fma.rn.f32x2 %0, %1, %2, %0;" : "+l"(acc) : "l"(a), "l"(b));
}
__device__ __forceinline__ float lo_f(unsigned long long v) {
    return __uint_as_float((unsigned)v);
}
__device__ __forceinline__ float hi_f(unsigned long long v) {
    return __uint_as_float((unsigned)(v >> 32));
}

// ---------------------------------------------------------------------------
// Fused distance-GEMM (packed f32x2 FMA) + argmin + gather.
// 512 threads, tile TM=64 x TN=256, microtile 4 rows x 8 cols (4 f32x2 pairs).
//   warp w (0..15) owns rows w*4..w*4+3 (A load = warp-broadcast LDS.128)
//   lane l owns cols l*4..l*4+3 and 128+l*4..+3 (B = 2x LDS.128 as u64 pairs)
// xs: [K=256][TM=64] k-major, resident (64 KB)
// es: double-buffered [BK=32][TN=256] k-major (2x32 KB), reg-prefetch, 1 sync/chunk
// ---------------------------------------------------------------------------
extern __shared__ float dyn_smem[];

__global__ __launch_bounds__(NTHREADS, 1) void vq_kernel(
    const float* __restrict__ x,
    const float* __restrict__ embed,
    float* __restrict__ out,
    int M, int N)
{
    float* xs   = dyn_smem;                     // [256][64]
    float* buf0 = dyn_smem + D * TM;            // [32][256]
    float* buf1 = buf0 + BK * TN;               // [32][256]

    __shared__ int best_row[TM];

    const int tid  = threadIdx.x;
    const int lane = tid & 31;
    const int warp = tid >> 5;
    const int rowBase = blockIdx.x * TM;

    // ---- Load x tile transposed: thread t -> row (t&63), 8 float4 section
    {
        int r    = tid & 63;
        int ksec = tid >> 6;                    // 0..7
        const float4* src = (const float4*)(x + (size_t)(rowBase + r) * D);
        #pragma unroll
        for (int kv = ksec * 8; kv < ksec * 8 + 8; kv++) {
            float4 v = src[kv];
            xs[(kv * 4 + 0) * TM + r] = v.x;
            xs[(kv * 4 + 1) * TM + r] = v.y;
            xs[(kv * 4 + 2) * TM + r] = v.z;
            xs[(kv * 4 + 3) * TM + r] = v.w;
        }
    }

    // chunk-load mapping: thread t -> row r = t>>1, half h = t&1 (4 float4)
    const int pr = tid >> 1;
    const int ph = tid & 1;

    float4 pf[4];
    // ---- chunk 0 (nt=0, kt=0)
    {
        const float4* p = (const float4*)(embed + (size_t)pr * D) + ph * 4;
        #pragma unroll
        for (int q = 0; q < 4; q++) pf[q] = p[q];
    }
    // store chunk 0 into buf0
    #pragma unroll
    for (int q = 0; q < 4; q++) {
        int klb = ph * 16 + q * 4;
        buf0[(klb + 0) * TN + pr] = pf[q].x;
        buf0[(klb + 1) * TN + pr] = pf[q].y;
        buf0[(klb + 2) * TN + pr] = pf[q].z;
        buf0[(klb + 3) * TN + pr] = pf[q].w;
    }
    __syncthreads();
    // ---- prefetch chunk 1 (nt=0, kt=1)
    {
        const float4* p = (const float4*)(embed + (size_t)pr * D) + 8 + ph * 4;
        #pragma unroll
        for (int q = 0; q < 4; q++) pf[q] = p[q];
    }

    float bestv[4];
    int   besti[4];
    #pragma unroll
    for (int i = 0; i < 4; i++) { bestv[i] = 3.4e38f; besti[i] = 0; }

    unsigned long long acc2[4][4];

    const int totalChunks = (N / TN) * (D / BK);       // 256

    for (int c = 0; c < totalChunks; c++) {
        float* cur = (c & 1) ? buf1 : buf0;
        float* nxt = (c & 1) ? buf0 : buf1;

        // store prefetched chunk c+1 (buffer parity (c+1)&1 was last read at
        // chunk c-1, whose compute finished before the sync ending iter c-1)
        if (c + 1 < totalChunks) {
            #pragma unroll
            for (int q = 0; q < 4; q++) {
                int klb = ph * 16 + q * 4;
                nxt[(klb + 0) * TN + pr] = pf[q].x;
                nxt[(klb + 1) * TN + pr] = pf[q].y;
                nxt[(klb + 2) * TN + pr] = pf[q].z;
                nxt[(klb + 3) * TN + pr] = pf[q].w;
            }
        }
        // issue LDGs for chunk c+2
        if (c + 2 < totalChunks) {
            int nc  = c + 2;
            int nnt = (nc >> 3) * TN;
            int nkt = nc & 7;
            const float4* p =
                (const float4*)(embed + (size_t)(nnt + pr) * D) + nkt * 8 + ph * 4;
            #pragma unroll
            for (int q = 0; q < 4; q++) pf[q] = p[q];
        }

        if ((c & 7) == 0) {
            #pragma unroll
            for (int i = 0; i < 4; i++)
                #pragma unroll
                for (int j = 0; j < 4; j++) acc2[i][j] = 0ull;
        }

        // ---- compute chunk c
        const float* xk = xs + (size_t)(c & 7) * BK * TM;
        #pragma unroll 8
        for (int kk = 0; kk < BK; kk++) {
            float4 A = *(const float4*)(xk + kk * TM + warp * 4);
            ulonglong2 B0 = *(const ulonglong2*)(cur + kk * TN + lane * 4);
            ulonglong2 B1 = *(const ulonglong2*)(cur + kk * TN + 128 + lane * 4);
            unsigned long long av[4];
            av[0] = pack_dup(A.x); av[1] = pack_dup(A.y);
            av[2] = pack_dup(A.z); av[3] = pack_dup(A.w);
            unsigned long long bv[4] = {B0.x, B0.y, B1.x, B1.y};
            #pragma unroll
            for (int i = 0; i < 4; i++)
                #pragma unroll
                for (int j = 0; j < 4; j++)
                    fma2(acc2[i][j], av[i], bv[j]);
        }

        // ---- tile epilogue: argmin update
        if ((c & 7) == 7) {
            int nt = (c >> 3) * TN;
            float eq[8];
            #pragma unroll
            for (int j = 0; j < 4; j++) {
                eq[j]     = __ldg(&g_esq[nt + lane * 4 + j]);
                eq[j + 4] = __ldg(&g_esq[nt + 128 + lane * 4 + j]);
            }
            #pragma unroll
            for (int i = 0; i < 4; i++) {
                #pragma unroll
                for (int jp = 0; jp < 4; jp++) {   // pair jp -> cols ascending
                    int cbase = (jp < 2) ? (nt + lane * 4 + jp * 2)
                                         : (nt + 128 + lane * 4 + (jp - 2) * 2);
                    float s0 = eq[(jp < 2) ? (jp * 2)     : (4 + (jp - 2) * 2)]
                               - 2.0f * lo_f(acc2[i][jp]);
                    float s1 = eq[(jp < 2) ? (jp * 2 + 1) : (5 + (jp - 2) * 2)]
                               - 2.0f * hi_f(acc2[i][jp]);
                    if (s0 < bestv[i]) { bestv[i] = s0; besti[i] = cbase; }
                    if (s1 < bestv[i]) { bestv[i] = s1; besti[i] = cbase + 1; }
                }
            }
        }
        __syncthreads();
    }

    // ---- warp-shuffle argmin reduce (rows owned entirely by one warp)
    #pragma unroll
    for (int i = 0; i < 4; i++) {
        float v  = bestv[i];
        int   ix = besti[i];
        #pragma unroll
        for (int off = 16; off; off >>= 1) {
            float ov = __shfl_xor_sync(0xFFFFFFFFu, v, off);
            int   oi = __shfl_xor_sync(0xFFFFFFFFu, ix, off);
            if (ov < v || (ov == v && oi < ix)) { v = ov; ix = oi; }
        }
        if (lane == 0) {
            int row = warp * 4 + i;
            best_row[row] = ix;
            out[(long long)M * D + rowBase + row] = (float)ix;
        }
    }
    __syncthreads();

    // ---- gather: quantized[row] = embed[best_idx[row]]
    for (int i = tid; i < TM * (D / 4); i += NTHREADS) {
        int r = i >> 6, kv = i & 63;
        float4 v = ((const float4*)(embed + (size_t)best_row[r] * D))[kv];
        ((float4*)(out + (size_t)(rowBase + r) * D))[kv] = v;
    }
}

// ---------------------------------------------------------------------------
extern "C" void kernel_launch(void* const* d_in, const int* in_sizes, int n_in,
                              void* d_out, int out_size)
{
    const float* x     = (const float*)d_in[0];
    const float* embed = (const float*)d_in[1];
    float*       out   = (float*)d_out;

    int M = in_sizes[0] / D;   // 8192 rows of x
    int N = in_sizes[1] / D;   // 8192 codes
    if (N > NMAX) N = NMAX;

    int esq_blocks = (N * 32 + 255) / 256;
    esq_kernel<<<esq_blocks, 256>>>(embed, N);

    size_t smem = (size_t)(D * TM + 2 * BK * TN) * sizeof(float);   // 128 KB
    cudaFuncSetAttribute(vq_kernel, cudaFuncAttributeMaxDynamicSharedMemorySize,
                         (int)smem);
    vq_kernel<<<M / TM, NTHREADS, smem>>>(x, embed, out, M, N);
}

// round 5
// speedup vs baseline: 1.3451x; 1.3451x over previous
#include <cuda_runtime.h>
#include <cstdint>

#define D_DIM   256
#define M_TOT   8192
#define N_TOT   8192
#define TM      64
#define TN      64
#define NTHREADS 256

// smem float offsets
#define AH_OFF  0
#define AL_OFF  16384
#define BH_OFF  32768
#define BL_OFF  41216
#define SM_FLOATS 49664                // 198,656 bytes
#define BSTRIDE 132                    // B row stride in floats (conflict-free frags)

__device__ float g_esq[N_TOT];

// ---------------------------------------------------------------------------
__device__ __forceinline__ float tf32_rn(float a) {
    uint32_t u;
    asm("cvt.rna.tf32.f32 %0, %1;" : "=r"(u) : "f"(a));
    return __uint_as_float(u);
}
__device__ __forceinline__ void mma1688(float* d, const uint32_t* a,
                                        const uint32_t* b) {
    asm volatile(
        "mma.sync.aligned.m16n8k8.row.col.f32.tf32.tf32.f32 "
        "{%0,%1,%2,%3}, {%4,%5,%6,%7}, {%8,%9}, {%0,%1,%2,%3};"
        : "+f"(d[0]), "+f"(d[1]), "+f"(d[2]), "+f"(d[3])
        : "r"(a[0]), "r"(a[1]), "r"(a[2]), "r"(a[3]), "r"(b[0]), "r"(b[1]));
}

// ---------------------------------------------------------------------------
__global__ void esq_kernel(const float* __restrict__ embed) {
    int w = (blockIdx.x * blockDim.x + threadIdx.x) >> 5;
    int lane = threadIdx.x & 31;
    if (w >= N_TOT) return;
    const float4* row = (const float4*)(embed + (size_t)w * D_DIM);
    float s = 0.f;
    #pragma unroll
    for (int i = lane; i < D_DIM / 4; i += 32) {
        float4 v = row[i];
        s += v.x * v.x + v.y * v.y + v.z * v.z + v.w * v.w;
    }
    #pragma unroll
    for (int o = 16; o; o >>= 1) s += __shfl_xor_sync(0xFFFFFFFFu, s, o);
    if (lane == 0) g_esq[w] = s;
}

// ---------------------------------------------------------------------------
// Fused 3xTF32 mma.sync GEMM + argmin + gather.
// CTA: 256 thr (8 warps, grid 2m x 4n), TM=64 rows resident, TN=64 streamed.
// A smem: fragment-permuted [4 mtiles][32 k8][128 floats], hi+lo (128 KB).
// B smem: k-major-ish [64 n][132 floats] per K=128 chunk, hi+lo (67.6 KB).
// ---------------------------------------------------------------------------
extern __shared__ float sm[];

__global__ __launch_bounds__(NTHREADS, 1) void vq_mma_kernel(
    const float* __restrict__ x,
    const float* __restrict__ embed,
    float* __restrict__ out)
{
    __shared__ unsigned long long red[TM];
    __shared__ int bestrow[TM];

    const int tid  = threadIdx.x;
    const int lane = tid & 31;
    const int wid  = tid >> 5;
    const int wm   = wid & 1;          // 0..1  (m)
    const int wn   = wid >> 1;         // 0..3  (n)
    const int mBase = blockIdx.x * TM;

    if (tid < TM) red[tid] = 0xFFFFFFFFFFFFFFFFull;

    // ---- A load (one-time): x rows -> tf32 hi/lo, mma-fragment-permuted
    #pragma unroll 4
    for (int s = 0; s < 16; s++) {
        int fidx = tid + s * NTHREADS;          // 0..4095 over 64x64 float4
        int row = fidx >> 6;
        int q   = fidx & 63;
        float4 v = ((const float4*)(x + (size_t)(mBase + row) * D_DIM))[q];
        int mt = row >> 4, ml = row & 15;
        float vv[4] = {v.x, v.y, v.z, v.w};
        #pragma unroll
        for (int e = 0; e < 4; e++) {
            int kk = q * 4 + e;
            float h = tf32_rn(vv[e]);
            float l = tf32_rn(vv[e] - h);
            int k8 = kk >> 3, c = kk & 7;
            int t    = ((ml & 7) << 2) | (c & 3);
            int slot = ((ml >> 3) & 1) | (((c >> 2) & 1) << 1);
            int off  = (mt * 32 + k8) * 128 + t * 4 + slot;
            sm[AH_OFF + off] = h;
            sm[AL_OFF + off] = l;
        }
    }

    // ---- B prefetch regs: 8 float4 per thread = one K=128 chunk share
    const int pn0 = tid >> 5;                   // base n (stride 8)
    const int pq  = tid & 31;                   // float4 index within chunk
    float4 pf[8];
    {   // chunk 0 = (ntile 0, kc 0)
        const float* bp = embed;
        #pragma unroll
        for (int s = 0; s < 8; s++)
            pf[s] = *(const float4*)(bp + (size_t)(pn0 + 8 * s) * D_DIM + pq * 4);
    }

    float bestv[4];
    int   besti[4];
    #pragma unroll
    for (int i = 0; i < 4; i++) { bestv[i] = 3.4e38f; besti[i] = 0; }

    const int nIter = N_TOT / TN;               // 128

    for (int nt = 0; nt < nIter; nt++) {
        float acc[2][2][4];
        #pragma unroll
        for (int a = 0; a < 2; a++)
            #pragma unroll
            for (int b = 0; b < 2; b++)
                #pragma unroll
                for (int j = 0; j < 4; j++) acc[a][b][j] = 0.f;

        for (int kc = 0; kc < 2; kc++) {
            __syncthreads();                    // prior chunk reads done
            // store prefetched chunk (cvt to hi/lo)
            #pragma unroll
            for (int s = 0; s < 8; s++) {
                int n = pn0 + 8 * s;
                float vv[4] = {pf[s].x, pf[s].y, pf[s].z, pf[s].w};
                float4 hv, lv;
                float* hp = (float*)&hv; float* lp = (float*)&lv;
                #pragma unroll
                for (int e = 0; e < 4; e++) {
                    float h = tf32_rn(vv[e]);
                    hp[e] = h; lp[e] = tf32_rn(vv[e] - h);
                }
                *(float4*)&sm[BH_OFF + n * BSTRIDE + pq * 4] = hv;
                *(float4*)&sm[BL_OFF + n * BSTRIDE + pq * 4] = lv;
            }
            __syncthreads();

            // prefetch next chunk
            int c = nt * 2 + kc + 1;
            if (c < nIter * 2) {
                const float* bp = embed + (size_t)((c >> 1) * TN) * D_DIM
                                        + (c & 1) * 128;
                #pragma unroll
                for (int s = 0; s < 8; s++)
                    pf[s] = *(const float4*)(bp + (size_t)(pn0 + 8 * s) * D_DIM
                                             + pq * 4);
            }

            // ---- compute 16 k8 steps
            #pragma unroll 4
            for (int k8 = 0; k8 < 16; k8++) {
                int k8g = kc * 16 + k8;
                uint32_t aH[2][4], aL[2][4];
                #pragma unroll
                for (int mt = 0; mt < 2; mt++) {
                    int mtg = wm * 2 + mt;
                    const uint4* p = (const uint4*)&sm[AH_OFF +
                        (mtg * 32 + k8g) * 128 + lane * 4];
                    uint4 v = *p;
                    aH[mt][0] = v.x; aH[mt][1] = v.y; aH[mt][2] = v.z; aH[mt][3] = v.w;
                    const uint4* p2 = (const uint4*)&sm[AL_OFF +
                        (mtg * 32 + k8g) * 128 + lane * 4];
                    uint4 v2 = *p2;
                    aL[mt][0] = v2.x; aL[mt][1] = v2.y; aL[mt][2] = v2.z; aL[mt][3] = v2.w;
                }
                uint32_t bH[2][2], bL[2][2];
                #pragma unroll
                for (int ntl = 0; ntl < 2; ntl++) {
                    int nrow = wn * 16 + ntl * 8 + (lane >> 2);
                    int kidx = k8 * 8 + (lane & 3);
                    bH[ntl][0] = __float_as_uint(sm[BH_OFF + nrow * BSTRIDE + kidx]);
                    bH[ntl][1] = __float_as_uint(sm[BH_OFF + nrow * BSTRIDE + kidx + 4]);
                    bL[ntl][0] = __float_as_uint(sm[BL_OFF + nrow * BSTRIDE + kidx]);
                    bL[ntl][1] = __float_as_uint(sm[BL_OFF + nrow * BSTRIDE + kidx + 4]);
                }
                #pragma unroll
                for (int mt = 0; mt < 2; mt++)
                    #pragma unroll
                    for (int ntl = 0; ntl < 2; ntl++) {
                        mma1688(acc[mt][ntl], aH[mt], bH[ntl]);   // hi*hi
                        mma1688(acc[mt][ntl], aH[mt], bL[ntl]);   // hi*lo
                        mma1688(acc[mt][ntl], aL[mt], bH[ntl]);   // lo*hi
                    }
            }
        }

        // ---- epilogue: per-thread argmin update
        #pragma unroll
        for (int mt = 0; mt < 2; mt++) {
            #pragma unroll
            for (int ntl = 0; ntl < 2; ntl++) {
                int c0 = nt * TN + wn * 16 + ntl * 8 + 2 * (lane & 3);
                float e0 = __ldg(&g_esq[c0]);
                float e1 = __ldg(&g_esq[c0 + 1]);
                // rows r (d0,d1) and r+8 (d2,d3)
                float s0 = e0 - 2.0f * acc[mt][ntl][0];
                float s1 = e1 - 2.0f * acc[mt][ntl][1];
                float s2 = e0 - 2.0f * acc[mt][ntl][2];
                float s3 = e1 - 2.0f * acc[mt][ntl][3];
                int bl = mt * 2, bh = mt * 2 + 1;
                if (s0 < bestv[bl]) { bestv[bl] = s0; besti[bl] = c0; }
                if (s1 < bestv[bl]) { bestv[bl] = s1; besti[bl] = c0 + 1; }
                if (s2 < bestv[bh]) { bestv[bh] = s2; besti[bh] = c0; }
                if (s3 < bestv[bh]) { bestv[bh] = s3; besti[bh] = c0 + 1; }
            }
        }
    }

    // ---- CTA-wide reduce via packed (orderable score | idx) smem atomicMin
    __syncthreads();
    #pragma unroll
    for (int i = 0; i < 4; i++) {
        int mt = i >> 1, h = i & 1;
        int r = wm * 32 + mt * 16 + (lane >> 2) + h * 8;
        uint32_t u = __float_as_uint(bestv[i]);
        u = (u & 0x80000000u) ? ~u : (u | 0x80000000u);
        unsigned long long key =
            ((unsigned long long)u << 32) | (uint32_t)besti[i];
        atomicMin(&red[r], key);
    }
    __syncthreads();

    if (tid < TM) {
        int idx = (int)(red[tid] & 0xFFFFFFFFull);
        bestrow[tid] = idx;
        out[(long long)M_TOT * D_DIM + mBase + tid] = (float)idx;
    }
    __syncthreads();

    // ---- gather (exact fp32 rows from embed)
    for (int i = tid; i < TM * (D_DIM / 4); i += NTHREADS) {
        int r = i >> 6, kv = i & 63;
        float4 v = ((const float4*)(embed + (size_t)bestrow[r] * D_DIM))[kv];
        ((float4*)(out + (size_t)(mBase + r) * D_DIM))[kv] = v;
    }
}

// ---------------------------------------------------------------------------
extern "C" void kernel_launch(void* const* d_in, const int* in_sizes, int n_in,
                              void* d_out, int out_size)
{
    const float* x     = (const float*)d_in[0];
    const float* embed = (const float*)d_in[1];
    float*       out   = (float*)d_out;

    esq_kernel<<<(N_TOT * 32 + 255) / 256, 256>>>(embed);

    cudaFuncSetAttribute(vq_mma_kernel,
                         cudaFuncAttributeMaxDynamicSharedMemorySize,
                         SM_FLOATS * 4);
    vq_mma_kernel<<<M_TOT / TM, NTHREADS, SM_FLOATS * 4>>>(x, embed, out);
}